// round 7
// baseline (speedup 1.0000x reference)
#include <cuda_runtime.h>
#include <mma.h>
#include <math.h>

using namespace nvcuda;

// Problem constants
#define TT    256
#define BSZ   64
#define DIN   1024
#define HIDN  1024
#define NL    2
#define H4    (4 * HIDN)
#define MTOT  (TT * BSZ)          // 16384
#define BH    (BSZ * HIDN)        // 65536

#define NCTA  128                 // persistent CTAs, 1 per SM
#define UPC   8                   // hidden units per CTA; 32 gate-cols per CTA
#define NTHR  512                 // 16 warps: 2 K-halves x 4 batch-tiles x 2 col-tiles

// ---------------- device scratch (no allocations allowed) ----------------
__device__ float g_Xp[(size_t)MTOT * H4];   // precomputed x@Wx^T + b for current layer
__device__ float g_H0[(size_t)MTOT * HIDN]; // layer-0 hidden outputs for all t
__device__ float g_c[NL][BH];               // final cell states
__device__ unsigned g_bar;                  // grid barrier counter

__global__ void reset_bar_kernel() {
    if (threadIdx.x == 0) g_bar = 0u;
}

// ---------------- precompute GEMM: C = A[M,K] @ W[N,K]^T + bias[N] -> g_Xp ----------------
__global__ void gemm_xp_kernel(const float* __restrict__ A,
                               const float* __restrict__ W,
                               const float* __restrict__ bias,
                               int M, int N, int K) {
    __shared__ float As[64][36];
    __shared__ float Ws[64][36];
    __shared__ float Cs[64][68];

    const int tid  = threadIdx.x;
    const int warp = tid >> 5;
    const int wm   = warp & 3;
    const int wn   = warp >> 2;
    const int row0A = blockIdx.y * 64;
    const int row0W = blockIdx.x * 64;

    wmma::fragment<wmma::accumulator, 16, 16, 8, float> acc[2];
    wmma::fill_fragment(acc[0], 0.f);
    wmma::fill_fragment(acc[1], 0.f);

    for (int k0 = 0; k0 < K; k0 += 32) {
#pragma unroll
        for (int r = 0; r < 2; r++) {
            int row = r * 32 + (tid >> 3);
            int c4  = (tid & 7) * 4;
            *(float4*)&As[row][c4] =
                *(const float4*)(A + (size_t)(row0A + row) * K + k0 + c4);
            *(float4*)&Ws[row][c4] =
                *(const float4*)(W + (size_t)(row0W + row) * K + k0 + c4);
        }
        __syncthreads();
#pragma unroll
        for (int kk = 0; kk < 32; kk += 8) {
            wmma::fragment<wmma::matrix_a, 16, 16, 8, wmma::precision::tf32, wmma::row_major> af;
            wmma::load_matrix_sync(af, &As[wm * 16][kk], 36);
#pragma unroll
            for (int i = 0; i < af.num_elements; i++) af.x[i] = wmma::__float_to_tf32(af.x[i]);
#pragma unroll
            for (int j = 0; j < 2; j++) {
                wmma::fragment<wmma::matrix_b, 16, 16, 8, wmma::precision::tf32, wmma::col_major> bf;
                wmma::load_matrix_sync(bf, &Ws[wn * 32 + j * 16][kk], 36);
#pragma unroll
                for (int i = 0; i < bf.num_elements; i++) bf.x[i] = wmma::__float_to_tf32(bf.x[i]);
                wmma::mma_sync(acc[j], af, bf, acc[j]);
            }
        }
        __syncthreads();
    }

    wmma::store_matrix_sync(&Cs[wm * 16][wn * 32],      acc[0], 68, wmma::mem_row_major);
    wmma::store_matrix_sync(&Cs[wm * 16][wn * 32 + 16], acc[1], 68, wmma::mem_row_major);
    __syncthreads();

    for (int idx = tid; idx < 64 * 64; idx += 256) {
        int r = idx >> 6, c = idx & 63;
        g_Xp[(size_t)(row0A + r) * N + row0W + c] = Cs[r][c] + bias[row0W + c];
    }
}

// ---------------- persistent recurrence ----------------
// 128 CTAs x 512 threads. CTA owns 8 hidden units (32 gate-cols). Wh slice in
// SMEM (loaded once, 132 KB). A-operand h(t-1) is loaded DIRECTLY from global
// by wmma::load_matrix_sync — no SMEM staging, no intra-step __syncthreads.
// 16 warps: wk = K-half (512), wm = 16-batch tile, wn = 16-col tile.
// 64 mmas per warp per step, 2 alternating accumulators, partials summed in Gs.
//
// SMEM floats:
//   Ws : 32 x 1032                      = 33024  (132 KB)
//   Gs : 64 x 72 (two K-half 32-col)    =  4608
//   cs : 512                            =   512
#define SM_WS 0
#define SM_GS (SM_WS + 32 * 1032)
#define SM_CS (SM_GS + 64 * 72)
#define SM_FLOATS (SM_CS + 512)

__global__ void __launch_bounds__(NTHR, 1)
lstm_seq_kernel(const float* __restrict__ Wh,   // [H4, HIDN] layer base
                const float* __restrict__ Xp,   // [TT, BSZ, H4]
                float* Htraj,                   // [TT, BSZ, HIDN]
                float* __restrict__ gC) {       // [BSZ, HIDN] final cell out
    extern __shared__ float sm[];
    float* Ws = sm + SM_WS;
    float* Gs = sm + SM_GS;
    float* cs = sm + SM_CS;

    const int tid  = threadIdx.x;
    const int warp = tid >> 5;
    const int wk   = warp >> 3;        // 0..1 K-half
    const int wm   = (warp >> 1) & 3;  // 0..3 batch tile
    const int wn   = warp & 1;         // 0..1 col tile
    const int j0   = blockIdx.x * UPC;

    // ---- preload Wh slice: smem row n (0..31) = gate (n>>3), unit (n&7) ----
    for (int i4 = tid; i4 < 32 * 256; i4 += NTHR) {
        int n  = i4 >> 8;
        int c4 = (i4 & 255) * 4;
        int row = (n >> 3) * HIDN + j0 + (n & 7);
        *(float4*)&Ws[n * 1032 + c4] = *(const float4*)(Wh + (size_t)row * HIDN + c4);
    }
    if (tid < 512) cs[tid] = 0.f;
    __syncthreads();

    // epilogue mapping: one element per thread
    const int eb = tid >> 3;       // batch 0..63
    const int eu = tid & 7;        // unit 0..7

    // per-warp constant base pointers
    const float* Ws_base = Ws + (size_t)(wn * 16) * 1032 + wk * 512;

    for (int t = 0; t < TT; t++) {
        // prefetch Xp gate pre-activations for this thread's element (DRAM)
        const float* xb = Xp + (size_t)t * BSZ * H4 + (size_t)eb * H4 + j0 + eu;
        float x_i = xb[0];
        float x_f = xb[HIDN];
        float x_o = xb[2 * HIDN];
        float x_c = xb[3 * HIDN];

        wmma::fragment<wmma::accumulator, 16, 16, 8, float> acc[2];
        wmma::fill_fragment(acc[0], 0.f);
        wmma::fill_fragment(acc[1], 0.f);

        if (t > 0) {
            // A operand directly from global: rows (wm*16 .. wm*16+15), K-half wk
            const float* Ag = Htraj + (size_t)(t - 1) * BH
                            + (size_t)(wm * 16) * HIDN + wk * 512;
#pragma unroll 8
            for (int kc = 0; kc < 64; kc++) {
                wmma::fragment<wmma::matrix_a, 16, 16, 8, wmma::precision::tf32, wmma::row_major> af;
                wmma::load_matrix_sync(af, Ag + kc * 8, HIDN);
#pragma unroll
                for (int i = 0; i < af.num_elements; i++) af.x[i] = wmma::__float_to_tf32(af.x[i]);
                wmma::fragment<wmma::matrix_b, 16, 16, 8, wmma::precision::tf32, wmma::col_major> bf;
                wmma::load_matrix_sync(bf, Ws_base + kc * 8, 1032);
#pragma unroll
                for (int i = 0; i < bf.num_elements; i++) bf.x[i] = wmma::__float_to_tf32(bf.x[i]);
                wmma::mma_sync(acc[kc & 1], af, bf, acc[kc & 1]);
            }
        }

        // sum the two local accumulators, store K-half partial to Gs
#pragma unroll
        for (int i = 0; i < acc[0].num_elements; i++) acc[0].x[i] += acc[1].x[i];
        wmma::store_matrix_sync(&Gs[(wm * 16) * 72 + wk * 36 + wn * 16], acc[0], 72,
                                wmma::mem_row_major);
        __syncthreads();

        // ---- LSTM cell epilogue: one element per thread ----
        {
            float gi = Gs[eb * 72 + eu]      + Gs[eb * 72 + 36 + eu]      + x_i;
            float gf = Gs[eb * 72 + 8 + eu]  + Gs[eb * 72 + 36 + 8 + eu]  + x_f;
            float go = Gs[eb * 72 + 16 + eu] + Gs[eb * 72 + 36 + 16 + eu] + x_o;
            float gc = Gs[eb * 72 + 24 + eu] + Gs[eb * 72 + 36 + 24 + eu] + x_c;
            float si = 1.f / (1.f + expf(-gi));
            float sf = 1.f / (1.f + expf(-gf));
            float so = 1.f / (1.f + expf(-go));
            float cn = sf * cs[tid] + si * tanhf(gc);
            cs[tid] = cn;
            Htraj[(size_t)t * BH + (size_t)eb * HIDN + j0 + eu] = so * tanhf(cn);
        }

        // ---- grid barrier: release h(t) to all CTAs ----
        __threadfence();
        __syncthreads();
        if (tid == 0) {
            atomicAdd(&g_bar, 1u);
            unsigned target = (unsigned)(t + 1) * NCTA;
            while (*((volatile unsigned*)&g_bar) < target) { }
        }
        __syncthreads();
        __threadfence();
    }

    // ---- final cell state ----
    gC[(size_t)eb * HIDN + j0 + eu] = cs[tid];
}

// ---------------- finalize: Hf / Cf ----------------
__global__ void finalize_kernel(const float* __restrict__ h0_last,
                                const float* __restrict__ h1_last,
                                float* __restrict__ Hf,
                                float* __restrict__ Cf) {
    int i = blockIdx.x * blockDim.x + threadIdx.x;
    if (i < BH) {
        Hf[i]      = h0_last[i];
        Hf[BH + i] = h1_last[i];
        Cf[i]      = g_c[0][i];
        Cf[BH + i] = g_c[1][i];
    }
}

// ---------------- launch ----------------
extern "C" void kernel_launch(void* const* d_in, const int* in_sizes, int n_in,
                              void* d_out, int out_size) {
    const float* X    = (const float*)d_in[0]; // [T, B, D]
    const float* Wx   = (const float*)d_in[1]; // [L, 4H, D]
    const float* Wh   = (const float*)d_in[2]; // [L, 4H, H]
    const float* bias = (const float*)d_in[3]; // [L, 4H]

    float* out     = (float*)d_out;
    float* outputs = out;                              // [T, B, H]
    float* Hf      = out + (size_t)TT * BSZ * HIDN;
    float* Cf      = Hf + (size_t)NL * BH;

    float *Xp_p = nullptr, *H0_p = nullptr, *gc_p = nullptr;
    cudaGetSymbolAddress((void**)&Xp_p, g_Xp);
    cudaGetSymbolAddress((void**)&H0_p, g_H0);
    cudaGetSymbolAddress((void**)&gc_p, g_c);

    static bool attr_set = false;
    if (!attr_set) {
        cudaFuncSetAttribute(lstm_seq_kernel,
                             cudaFuncAttributeMaxDynamicSharedMemorySize,
                             SM_FLOATS * sizeof(float));
        attr_set = true;
    }

    dim3 gg(H4 / 64, MTOT / 64);

    // Layer 0
    gemm_xp_kernel<<<gg, 256>>>(X, Wx, bias, MTOT, H4, DIN);
    reset_bar_kernel<<<1, 32>>>();
    lstm_seq_kernel<<<NCTA, NTHR, SM_FLOATS * sizeof(float)>>>(
        Wh, Xp_p, H0_p, gc_p);

    // Layer 1
    gemm_xp_kernel<<<gg, 256>>>(H0_p, Wx + (size_t)H4 * DIN, bias + H4, MTOT, H4, HIDN);
    reset_bar_kernel<<<1, 32>>>();
    lstm_seq_kernel<<<NCTA, NTHR, SM_FLOATS * sizeof(float)>>>(
        Wh + (size_t)H4 * HIDN, Xp_p, outputs, gc_p + BH);

    finalize_kernel<<<(BH + 255) / 256, 256>>>(
        H0_p + (size_t)(TT - 1) * BH,
        outputs + (size_t)(TT - 1) * BH,
        Hf, Cf);
}

// round 8
// speedup vs baseline: 1.3669x; 1.3669x over previous
#include <cuda_runtime.h>
#include <cuda_pipeline.h>
#include <mma.h>
#include <math.h>

using namespace nvcuda;

// Problem constants
#define TT    256
#define BSZ   64
#define DIN   1024
#define HIDN  1024
#define NL    2
#define H4    (4 * HIDN)
#define MTOT  (TT * BSZ)          // 16384
#define BH    (BSZ * HIDN)        // 65536

#define NCTA  128                 // persistent CTAs, 1 per SM
#define UPC   8                   // hidden units per CTA; 32 gate-cols per CTA
#define NTHR  512                 // 16 warps: 2 K-halves x 4 batch-tiles x 2 col-tiles

// ---------------- device scratch (no allocations allowed) ----------------
__device__ float g_Xp[(size_t)MTOT * H4];   // precomputed x@Wx^T + b
__device__ float g_H0[(size_t)MTOT * HIDN]; // layer-0 hidden outputs
__device__ float g_c[NL][BH];               // final cell states
__device__ unsigned g_bar;                  // grid barrier counter

__global__ void reset_bar_kernel() {
    if (threadIdx.x == 0) g_bar = 0u;
}

// ---------------- precompute GEMM: C = A[M,K] @ W[N,K]^T + bias[N] -> g_Xp ----------------
// 128x64 block tile, 256 threads (8 warps: 4 m x 2 n, each 32x32 = 4 wmma accs),
// K-chunk 32, double-buffered cp.async staging.
// dyn smem: 2 buffers x (As 128x36 + Ws 64x36) floats = 55296 B; Cs reuses it.
#define GX_BUF_FLOATS ((128 + 64) * 36)

__global__ void __launch_bounds__(256, 2)
gemm_xp_kernel(const float* __restrict__ A,
               const float* __restrict__ W,
               const float* __restrict__ bias,
               int M, int N, int K) {
    extern __shared__ float gsm[];

    const int tid  = threadIdx.x;
    const int warp = tid >> 5;
    const int wm   = warp & 3;      // m tile: wm*32
    const int wn   = warp >> 2;     // n tile: wn*32
    const int row0A = blockIdx.y * 128;
    const int row0W = blockIdx.x * 64;

    wmma::fragment<wmma::accumulator, 16, 16, 8, float> acc[2][2];
#pragma unroll
    for (int i = 0; i < 2; i++)
#pragma unroll
        for (int j = 0; j < 2; j++) wmma::fill_fragment(acc[i][j], 0.f);

    const int nchunks = K / 32;

    // stage helper (lambda-free, macro-ish via inline loop)
    // A: 128 rows x 8 float4; W: 64 rows x 8 float4
#define GX_STAGE(buf, kt)                                                          \
    {                                                                              \
        float* As_ = gsm + (buf) * GX_BUF_FLOATS;                                  \
        float* Ws_ = As_ + 128 * 36;                                               \
        int k0_ = (kt) * 32;                                                       \
        _Pragma("unroll")                                                          \
        for (int i_ = 0; i_ < 4; i_++) {                                           \
            int e_ = tid + i_ * 256;                                               \
            int r_ = e_ >> 3, c4_ = (e_ & 7) * 4;                                  \
            __pipeline_memcpy_async(&As_[r_ * 36 + c4_],                           \
                A + (size_t)(row0A + r_) * K + k0_ + c4_, 16);                     \
        }                                                                          \
        _Pragma("unroll")                                                          \
        for (int i_ = 0; i_ < 2; i_++) {                                           \
            int e_ = tid + i_ * 256;                                               \
            int r_ = e_ >> 3, c4_ = (e_ & 7) * 4;                                  \
            __pipeline_memcpy_async(&Ws_[r_ * 36 + c4_],                           \
                W + (size_t)(row0W + r_) * K + k0_ + c4_, 16);                     \
        }                                                                          \
    }

    GX_STAGE(0, 0);
    __pipeline_commit();

    for (int kt = 0; kt < nchunks; kt++) {
        int cur = kt & 1;
        __pipeline_wait_prior(0);
        __syncthreads();
        if (kt + 1 < nchunks) {
            GX_STAGE(cur ^ 1, kt + 1);
            __pipeline_commit();
        }
        float* As_ = gsm + cur * GX_BUF_FLOATS;
        float* Ws_ = As_ + 128 * 36;
#pragma unroll
        for (int kk = 0; kk < 32; kk += 8) {
            wmma::fragment<wmma::matrix_a, 16, 16, 8, wmma::precision::tf32, wmma::row_major> af[2];
            wmma::fragment<wmma::matrix_b, 16, 16, 8, wmma::precision::tf32, wmma::col_major> bf[2];
#pragma unroll
            for (int i = 0; i < 2; i++) {
                wmma::load_matrix_sync(af[i], &As_[(wm * 32 + i * 16) * 36 + kk], 36);
#pragma unroll
                for (int e = 0; e < af[i].num_elements; e++) af[i].x[e] = wmma::__float_to_tf32(af[i].x[e]);
            }
#pragma unroll
            for (int j = 0; j < 2; j++) {
                wmma::load_matrix_sync(bf[j], &Ws_[(wn * 32 + j * 16) * 36 + kk], 36);
#pragma unroll
                for (int e = 0; e < bf[j].num_elements; e++) bf[j].x[e] = wmma::__float_to_tf32(bf[j].x[e]);
            }
#pragma unroll
            for (int i = 0; i < 2; i++)
#pragma unroll
                for (int j = 0; j < 2; j++)
                    wmma::mma_sync(acc[i][j], af[i], bf[j], acc[i][j]);
        }
        __syncthreads();
    }

    // epilogue: reuse smem as Cs[128][68]
    float* Cs = gsm;
    __syncthreads();
#pragma unroll
    for (int i = 0; i < 2; i++)
#pragma unroll
        for (int j = 0; j < 2; j++)
            wmma::store_matrix_sync(&Cs[(wm * 32 + i * 16) * 68 + wn * 32 + j * 16],
                                    acc[i][j], 68, wmma::mem_row_major);
    __syncthreads();

    for (int idx = tid; idx < 128 * 64; idx += 256) {
        int r = idx >> 6, c = idx & 63;
        g_Xp[(size_t)(row0A + r) * N + row0W + c] = Cs[r * 68 + c] + bias[row0W + c];
    }
#undef GX_STAGE
}

// ---------------- persistent recurrence ----------------
// 128 CTAs x 512 threads. CTA owns 8 hidden units (32 gate-cols). Wh slice in
// SMEM (132 KB, loaded once). h(t-1) staged per step as 8 chunks of K=128 via
// cp.async into a double buffer. 16 warps: wk = K-half-of-chunk, wm = batch
// tile, wn = col tile. Grid barrier (release/acquire) between steps.
//
// SMEM floats:
//   Ws : 32 x 1032                = 33024
//   Hs : 2 x (64 x 132)           = 16896
//   Gs : 64 x 72                  =  4608
//   cs : 512                      =   512     total 55040 floats = 220160 B
#define SM_WS 0
#define SM_HS (SM_WS + 32 * 1032)
#define SM_GS (SM_HS + 2 * 64 * 132)
#define SM_CS (SM_GS + 64 * 72)
#define SM_FLOATS (SM_CS + 512)

__global__ void __launch_bounds__(NTHR, 1)
lstm_seq_kernel(const float* __restrict__ Wh,   // [H4, HIDN] layer base
                const float* __restrict__ Xp,   // [TT, BSZ, H4]
                float* Htraj,                   // [TT, BSZ, HIDN]
                float* __restrict__ gC) {       // [BSZ, HIDN] final cell out
    extern __shared__ float sm[];
    float* Ws = sm + SM_WS;
    float* Hs = sm + SM_HS;
    float* Gs = sm + SM_GS;
    float* cs = sm + SM_CS;

    const int tid  = threadIdx.x;
    const int warp = tid >> 5;
    const int wk   = warp >> 3;        // 0..1 K-half of each 128 chunk
    const int wm   = (warp >> 1) & 3;  // 0..3 batch tile
    const int wn   = warp & 1;         // 0..1 col tile
    const int j0   = blockIdx.x * UPC;

    // ---- preload Wh slice: smem row n (0..31) = gate (n>>3), unit (n&7) ----
    for (int i4 = tid; i4 < 32 * 256; i4 += NTHR) {
        int n  = i4 >> 8;
        int c4 = (i4 & 255) * 4;
        int row = (n >> 3) * HIDN + j0 + (n & 7);
        *(float4*)&Ws[n * 1032 + c4] = *(const float4*)(Wh + (size_t)row * HIDN + c4);
    }
    cs[tid] = 0.f;
    __syncthreads();

    // staging mapping: chunk = 64 rows x 32 float4; 512 threads -> 4 float4 each
    const int srow = tid >> 3;          // 0..63
    const int sc4  = (tid & 7) * 4;     // 0..28 step 4 (covers 32 of 128 cols; x4 passes)

    // epilogue mapping
    const int eb = tid >> 3;
    const int eu = tid & 7;

    const float* Ws_warp = Ws + (size_t)(wn * 16) * 1032;

    // x prefetch for t=0
    float x_i, x_f, x_o, x_c;
    {
        const float* xb = Xp + (size_t)eb * H4 + j0 + eu;
        x_i = xb[0]; x_f = xb[HIDN]; x_o = xb[2 * HIDN]; x_c = xb[3 * HIDN];
    }

    for (int t = 0; t < TT; t++) {
        wmma::fragment<wmma::accumulator, 16, 16, 8, float> acc[2];
        wmma::fill_fragment(acc[0], 0.f);
        wmma::fill_fragment(acc[1], 0.f);

        if (t > 0) {
            const float* Hprev = Htraj + (size_t)(t - 1) * BH;

#define H_STAGE(buf, it)                                                          \
            {                                                                     \
                float* Hb_ = Hs + (buf) * (64 * 132);                             \
                int k0_ = (it) * 128;                                             \
                _Pragma("unroll")                                                 \
                for (int p_ = 0; p_ < 4; p_++)                                    \
                    __pipeline_memcpy_async(&Hb_[srow * 132 + p_ * 32 + sc4],     \
                        Hprev + (size_t)srow * HIDN + k0_ + p_ * 32 + sc4, 16);   \
            }

            H_STAGE(0, 0);
            __pipeline_commit();

            for (int it = 0; it < 8; it++) {
                int cur = it & 1;
                __pipeline_wait_prior(0);
                __syncthreads();
                if (it < 7) {
                    H_STAGE(cur ^ 1, it + 1);
                    __pipeline_commit();
                }
                const float* Hb = Hs + cur * (64 * 132);
                const float* Wb = Ws_warp + it * 128 + wk * 64;
                const float* Ab = Hb + (wm * 16) * 132 + wk * 64;
#pragma unroll
                for (int kk = 0; kk < 64; kk += 8) {
                    wmma::fragment<wmma::matrix_a, 16, 16, 8, wmma::precision::tf32, wmma::row_major> af;
                    wmma::load_matrix_sync(af, Ab + kk, 132);
#pragma unroll
                    for (int i = 0; i < af.num_elements; i++) af.x[i] = wmma::__float_to_tf32(af.x[i]);
                    wmma::fragment<wmma::matrix_b, 16, 16, 8, wmma::precision::tf32, wmma::col_major> bf;
                    wmma::load_matrix_sync(bf, Wb + kk, 1032);
#pragma unroll
                    for (int i = 0; i < bf.num_elements; i++) bf.x[i] = wmma::__float_to_tf32(bf.x[i]);
                    wmma::mma_sync(acc[(kk >> 3) & 1], af, bf, acc[(kk >> 3) & 1]);
                }
            }
            __syncthreads();
#undef H_STAGE
        }

        // sum local accumulators; store K-half partial
#pragma unroll
        for (int i = 0; i < acc[0].num_elements; i++) acc[0].x[i] += acc[1].x[i];
        wmma::store_matrix_sync(&Gs[(wm * 16) * 72 + wk * 36 + wn * 16], acc[0], 72,
                                wmma::mem_row_major);
        __syncthreads();

        // ---- LSTM cell epilogue ----
        {
            float gi = Gs[eb * 72 + eu]      + Gs[eb * 72 + 36 + eu]      + x_i;
            float gf = Gs[eb * 72 + 8 + eu]  + Gs[eb * 72 + 36 + 8 + eu]  + x_f;
            float go = Gs[eb * 72 + 16 + eu] + Gs[eb * 72 + 36 + 16 + eu] + x_o;
            float gc = Gs[eb * 72 + 24 + eu] + Gs[eb * 72 + 36 + 24 + eu] + x_c;
            float si = 1.f / (1.f + expf(-gi));
            float sf = 1.f / (1.f + expf(-gf));
            float so = 1.f / (1.f + expf(-go));
            float cn = sf * cs[tid] + si * tanhf(gc);
            cs[tid] = cn;
            Htraj[(size_t)t * BH + (size_t)eb * HIDN + j0 + eu] = so * tanhf(cn);
        }

        // prefetch next step's x (overlaps the barrier spin)
        if (t + 1 < TT) {
            const float* xb = Xp + (size_t)(t + 1) * BSZ * H4 + (size_t)eb * H4 + j0 + eu;
            x_i = xb[0]; x_f = xb[HIDN]; x_o = xb[2 * HIDN]; x_c = xb[3 * HIDN];
        }

        // ---- grid barrier: release h(t), acquire all CTAs' h(t) ----
        __syncthreads();
        if (tid == 0) {
            asm volatile("red.release.gpu.global.add.u32 [%0], %1;"
                         :: "l"(&g_bar), "r"(1u) : "memory");
            unsigned target = (unsigned)(t + 1) * NCTA;
            unsigned v;
            do {
                asm volatile("ld.acquire.gpu.global.u32 %0, [%1];"
                             : "=r"(v) : "l"(&g_bar) : "memory");
            } while (v < target);
        }
        __syncthreads();
    }

    // ---- final cell state ----
    gC[(size_t)eb * HIDN + j0 + eu] = cs[tid];
}

// ---------------- finalize: Hf / Cf ----------------
__global__ void finalize_kernel(const float* __restrict__ h0_last,
                                const float* __restrict__ h1_last,
                                float* __restrict__ Hf,
                                float* __restrict__ Cf) {
    int i = blockIdx.x * blockDim.x + threadIdx.x;
    if (i < BH) {
        Hf[i]      = h0_last[i];
        Hf[BH + i] = h1_last[i];
        Cf[i]      = g_c[0][i];
        Cf[BH + i] = g_c[1][i];
    }
}

// ---------------- launch ----------------
extern "C" void kernel_launch(void* const* d_in, const int* in_sizes, int n_in,
                              void* d_out, int out_size) {
    const float* X    = (const float*)d_in[0]; // [T, B, D]
    const float* Wx   = (const float*)d_in[1]; // [L, 4H, D]
    const float* Wh   = (const float*)d_in[2]; // [L, 4H, H]
    const float* bias = (const float*)d_in[3]; // [L, 4H]

    float* out     = (float*)d_out;
    float* outputs = out;                              // [T, B, H]
    float* Hf      = out + (size_t)TT * BSZ * HIDN;
    float* Cf      = Hf + (size_t)NL * BH;

    float *Xp_p = nullptr, *H0_p = nullptr, *gc_p = nullptr;
    cudaGetSymbolAddress((void**)&Xp_p, g_Xp);
    cudaGetSymbolAddress((void**)&H0_p, g_H0);
    cudaGetSymbolAddress((void**)&gc_p, g_c);

    static bool attr_set = false;
    if (!attr_set) {
        cudaFuncSetAttribute(lstm_seq_kernel,
                             cudaFuncAttributeMaxDynamicSharedMemorySize,
                             SM_FLOATS * sizeof(float));
        cudaFuncSetAttribute(gemm_xp_kernel,
                             cudaFuncAttributeMaxDynamicSharedMemorySize,
                             2 * GX_BUF_FLOATS * sizeof(float));
        attr_set = true;
    }

    dim3 gg(H4 / 64, MTOT / 128);
    size_t gx_smem = 2 * GX_BUF_FLOATS * sizeof(float);

    // Layer 0
    gemm_xp_kernel<<<gg, 256, gx_smem>>>(X, Wx, bias, MTOT, H4, DIN);
    reset_bar_kernel<<<1, 32>>>();
    lstm_seq_kernel<<<NCTA, NTHR, SM_FLOATS * sizeof(float)>>>(
        Wh, Xp_p, H0_p, gc_p);

    // Layer 1
    gemm_xp_kernel<<<gg, 256, gx_smem>>>(H0_p, Wx + (size_t)H4 * DIN, bias + H4, MTOT, H4, HIDN);
    reset_bar_kernel<<<1, 32>>>();
    lstm_seq_kernel<<<NCTA, NTHR, SM_FLOATS * sizeof(float)>>>(
        Wh + (size_t)H4 * HIDN, Xp_p, outputs, gc_p + BH);

    finalize_kernel<<<(BH + 255) / 256, 256>>>(
        H0_p + (size_t)(TT - 1) * BH,
        outputs + (size_t)(TT - 1) * BH,
        Hf, Cf);
}